// round 11
// baseline (speedup 1.0000x reference)
#include <cuda_runtime.h>

#define NPTS   100000
#define BATCH  4096
#define KSEL   10
#define TPB    128
#define RPB    8                        // rays per block (8-way load broadcast)
#define NSUB   (TPB / RPB)              // 16 subs partition the points
#define PSPLIT 2
#define SLICE  (NPTS / PSPLIT)          // 50000
#define GRID   ((BATCH / RPB) * PSPLIT) // 1024 blocks
#define UNR    8
#define CHPTS  (NSUB * UNR)             // 128 points per chunk per block
#define NCHUNK (SLICE / CHPTS)          // 390; tail = 80 points (5 per sub)

__device__ float4 g_packed[NPTS];                  // (-2x, -2y, -2z, |x|^2)
__device__ float  g_pd2 [PSPLIT * BATCH * KSEL];
__device__ int    g_pidx[PSPLIT * BATCH * KSEL];

__global__ __launch_bounds__(256)
void pack_kernel(const float* __restrict__ xyz)
{
    int i = blockIdx.x * 256 + threadIdx.x;
    if (i < NPTS) {
        float x = xyz[i * 3 + 0];
        float y = xyz[i * 3 + 1];
        float z = xyz[i * 3 + 2];
        float q = fmaf(x, x, fmaf(y, y, z * z));
        g_packed[i] = make_float4(-2.0f * x, -2.0f * y, -2.0f * z, q);
    }
}

__global__ __launch_bounds__(TPB, 6)    // 85-reg budget (validated no-spill)
void scan_kernel(const float* __restrict__ rays_o,
                 const float* __restrict__ rays_d)
{
    __shared__ float md2s [RPB * NSUB * KSEL];   // 5 KB
    __shared__ int   midxs[RPB * NSUB * KSEL];   // 5 KB
    __shared__ float sT[RPB];
    volatile float* sTv = sT;

    const int t       = threadIdx.x;
    const int rl      = t & (RPB - 1);           // ray within block
    const int sub     = t >> 3;                  // 0..15
    const int slice   = blockIdx.x & (PSPLIT - 1);
    const int rayBase = (blockIdx.x >> 1) * RPB;

    float cx, cy, cz, C;
    {
        int r = rayBase + rl;
        cx = fmaf(3.0f, rays_d[r * 3 + 0], rays_o[r * 3 + 0]);
        cy = fmaf(3.0f, rays_d[r * 3 + 1], rays_o[r * 3 + 1]);
        cz = fmaf(3.0f, rays_d[r * 3 + 2], rays_o[r * 3 + 2]);
        C  = cx * cx + cy * cy + cz * cz;
    }
    if (t < RPB) sT[t] = 3.0e38f;
    __syncthreads();

    float best[KSEL];
    int   bidx[KSEL];
#pragma unroll
    for (int j = 0; j < KSEL; j++) { best[j] = 3.0e38f; bidx[j] = 0; }
    float tloc = 3.0e38f;

    const int sliceLo = slice * SLICE;
    const float4* p = g_packed + sliceLo + sub;
    int pbase = sliceLo + sub;

#pragma unroll 1
    for (int c = 0; c < NCHUNK; c++) {
        // ---- BATCHED LOADS: all 8 LDG.128 issued before any dependent FMA ----
        float4 q0 = p[0 * NSUB];
        float4 q1 = p[1 * NSUB];
        float4 q2 = p[2 * NSUB];
        float4 q3 = p[3 * NSUB];
        float4 q4 = p[4 * NSUB];
        float4 q5 = p[5 * NSUB];
        float4 q6 = p[6 * NSUB];
        float4 q7 = p[7 * NSUB];
        float Tl = fminf(sTv[rl], tloc);         // independent of loads; fills the shadow

        float s0 = fmaf(cx, q0.x, fmaf(cy, q0.y, fmaf(cz, q0.z, q0.w)));
        float s1 = fmaf(cx, q1.x, fmaf(cy, q1.y, fmaf(cz, q1.z, q1.w)));
        float s2 = fmaf(cx, q2.x, fmaf(cy, q2.y, fmaf(cz, q2.z, q2.w)));
        float s3 = fmaf(cx, q3.x, fmaf(cy, q3.y, fmaf(cz, q3.z, q3.w)));
        float s4 = fmaf(cx, q4.x, fmaf(cy, q4.y, fmaf(cz, q4.z, q4.w)));
        float s5 = fmaf(cx, q5.x, fmaf(cy, q5.y, fmaf(cz, q5.z, q5.w)));
        float s6 = fmaf(cx, q6.x, fmaf(cy, q6.y, fmaf(cz, q6.z, q6.w)));
        float s7 = fmaf(cx, q7.x, fmaf(cy, q7.y, fmaf(cz, q7.z, q7.w)));

        float m = fminf(fminf(fminf(s0, s1), fminf(s2, s3)),
                        fminf(fminf(s4, s5), fminf(s6, s7)));
        if (m < Tl) {
            float sv[UNR] = { s0, s1, s2, s3, s4, s5, s6, s7 };
#pragma unroll
            for (int u = 0; u < UNR; u++) {
                if (sv[u] < Tl) {
                    float v  = sv[u];
                    int   ii = pbase + u * NSUB;
#pragma unroll
                    for (int j = 0; j < KSEL; j++) {
                        if (v < best[j]) {
                            float tv = best[j]; int ti = bidx[j];
                            best[j] = v; bidx[j] = ii;
                            v = tv; ii = ti;
                        }
                    }
                    tloc = best[KSEL - 1];
                    Tl   = fminf(Tl, tloc);
                }
            }
            if (tloc < sTv[rl]) sTv[rl] = tloc;  // benign race: any stored value is a valid bound
        }
        p     += CHPTS;
        pbase += CHPTS;
    }
    // Tail: 5 points per sub
#pragma unroll 1
    for (int k = sliceLo + NCHUNK * CHPTS + sub; k < sliceLo + SLICE; k += NSUB) {
        float4 q = g_packed[k];
        float  s = fmaf(cx, q.x, fmaf(cy, q.y, fmaf(cz, q.z, q.w)));
        if (s < fminf(sTv[rl], tloc)) {
            float v = s; int ii = k;
#pragma unroll
            for (int j = 0; j < KSEL; j++) {
                if (v < best[j]) {
                    float tv = best[j]; int ti = bidx[j];
                    best[j] = v; bidx[j] = ii;
                    v = tv; ii = ti;
                }
            }
            tloc = best[KSEL - 1];
        }
    }

    const int lbase = (rl * NSUB + sub) * KSEL;
#pragma unroll
    for (int j = 0; j < KSEL; j++) {
        md2s[lbase + j]  = best[j] + C;
        midxs[lbase + j] = bidx[j];
    }

    // Tree merge: 16 sorted lists -> 1 per ray
    for (int stride = NSUB / 2; stride >= 1; stride >>= 1) {
        __syncthreads();
        if (sub < stride) {
            int a = (rl * NSUB + sub) * KSEL;
            int b = (rl * NSUB + sub + stride) * KSEL;
            float ov[KSEL]; int oi[KSEL];
            int ia = 0, ib = 0;
#pragma unroll
            for (int k = 0; k < KSEL; k++) {
                float va = md2s[a + ia], vb = md2s[b + ib];
                if (va <= vb) { ov[k] = va; oi[k] = midxs[a + ia]; ia++; }
                else          { ov[k] = vb; oi[k] = midxs[b + ib]; ib++; }
            }
#pragma unroll
            for (int k = 0; k < KSEL; k++) { md2s[a + k] = ov[k]; midxs[a + k] = oi[k]; }
        }
    }
    __syncthreads();

    if (t < RPB) {
        int src = (t * NSUB) * KSEL;
        int dst = (slice * BATCH + rayBase + t) * KSEL;
#pragma unroll
        for (int k = 0; k < KSEL; k++) {
            g_pd2 [dst + k] = md2s[src + k];
            g_pidx[dst + k] = midxs[src + k];
        }
    }
}

__global__ __launch_bounds__(128)
void finalize_kernel(const float* __restrict__ fdc,
                     const float* __restrict__ opac,
                     float* __restrict__ out)
{
    int ray = blockIdx.x * 128 + threadIdx.x;
    if (ray >= BATCH) return;
    int a = ray * KSEL, b = (BATCH + ray) * KSEL;
    int ia = 0, ib = 0;
    float wsum = 0.f, r0 = 0.f, g0 = 0.f, b0 = 0.f;
#pragma unroll
    for (int k = 0; k < KSEL; k++) {
        float va = (ia < KSEL) ? g_pd2[a + ia] : 3.0e38f;
        float vb = (ib < KSEL) ? g_pd2[b + ib] : 3.0e38f;
        float d2; int ii;
        if (va <= vb) { d2 = va; ii = g_pidx[a + ia]; ia++; }
        else          { d2 = vb; ii = g_pidx[b + ib]; ib++; }
        float d  = sqrtf(fmaxf(d2, 0.0f));
        float op = 1.0f / (1.0f + expf(-opac[ii]));
        float w  = expf(-0.1f * d) * op;
        wsum += w;
        float c0 = 1.0f / (1.0f + expf(-fdc[ii * 3 + 0]));
        float c1 = 1.0f / (1.0f + expf(-fdc[ii * 3 + 1]));
        float c2 = 1.0f / (1.0f + expf(-fdc[ii * 3 + 2]));
        r0 = fmaf(w, c0, r0);
        g0 = fmaf(w, c1, g0);
        b0 = fmaf(w, c2, b0);
    }
    float inv = 1.0f / (wsum + 1e-8f);
    out[ray * 3 + 0] = r0 * inv;
    out[ray * 3 + 1] = g0 * inv;
    out[ray * 3 + 2] = b0 * inv;
}

extern "C" void kernel_launch(void* const* d_in, const int* in_sizes, int n_in,
                              void* d_out, int out_size)
{
    const float* rays_o = (const float*)d_in[0];
    const float* rays_d = (const float*)d_in[1];
    const float* xyz    = (const float*)d_in[2];
    const float* fdc    = (const float*)d_in[3];
    const float* opac   = (const float*)d_in[4];
    float* out = (float*)d_out;

    pack_kernel<<<(NPTS + 255) / 256, 256>>>(xyz);
    scan_kernel<<<GRID, TPB>>>(rays_o, rays_d);
    finalize_kernel<<<BATCH / 128, 128>>>(fdc, opac, out);
}

// round 12
// speedup vs baseline: 1.0606x; 1.0606x over previous
#include <cuda_runtime.h>
#include <cstdint>

#define NPTS   100000
#define BATCH  4096
#define KSEL   10
#define TPB    128
#define RPB    8                        // rays per block
#define NSUB   (TPB / RPB)              // 16 subs partition the points
#define PSPLIT 2
#define SLICE  (NPTS / PSPLIT)          // 50000
#define GRID   ((BATCH / RPB) * PSPLIT) // 1024 blocks
#define UNR    8
#define CHPTS  (NSUB * UNR)             // 128 points per chunk per block
#define NCHUNK (SLICE / CHPTS)          // 390; tail = 80 points (5 per sub)
#define NSTG   4                        // cp.async pipeline depth

__device__ float4 g_packed[NPTS];                  // (-2x, -2y, -2z, |x|^2)
__device__ float  g_pd2 [PSPLIT * BATCH * KSEL];
__device__ int    g_pidx[PSPLIT * BATCH * KSEL];

__global__ __launch_bounds__(256)
void pack_kernel(const float* __restrict__ xyz)
{
    int i = blockIdx.x * 256 + threadIdx.x;
    if (i < NPTS) {
        float x = xyz[i * 3 + 0];
        float y = xyz[i * 3 + 1];
        float z = xyz[i * 3 + 2];
        float q = fmaf(x, x, fmaf(y, y, z * z));
        g_packed[i] = make_float4(-2.0f * x, -2.0f * y, -2.0f * z, q);
    }
}

__device__ __forceinline__ void cpasync16(uint32_t saddr, const void* gaddr) {
    asm volatile("cp.async.cg.shared.global [%0], [%1], 16;" :: "r"(saddr), "l"(gaddr));
}
__device__ __forceinline__ void cpcommit() {
    asm volatile("cp.async.commit_group;" ::: "memory");
}
__device__ __forceinline__ void cpwait3() {
    asm volatile("cp.async.wait_group 3;" ::: "memory");
}
__device__ __forceinline__ void cpwait0() {
    asm volatile("cp.async.wait_group 0;" ::: "memory");
}

__global__ __launch_bounds__(TPB, 8)
void scan_kernel(const float* __restrict__ rays_o,
                 const float* __restrict__ rays_d)
{
    // Warp-private staging ring: [warp][stage][slot] = 4*4*32 float4 = 8 KB
    __shared__ float4 stage[4 * NSTG * 32];
    __shared__ float  md2s [RPB * NSUB * KSEL];   // 5 KB
    __shared__ int    midxs[RPB * NSUB * KSEL];   // 5 KB
    __shared__ float  sT[RPB];
    volatile float* sTv = sT;

    const int t       = threadIdx.x;
    const int lane    = t & 31;
    const int w       = t >> 5;                  // warp 0..3
    const int rl      = t & (RPB - 1);           // ray within block
    const int sub     = t >> 3;                  // 0..15 (warp w covers 4w..4w+3)
    const int j       = sub & 3;                 // sub within warp
    const int slice   = blockIdx.x & (PSPLIT - 1);
    const int rayBase = (blockIdx.x >> 1) * RPB;

    float cx, cy, cz, C;
    {
        int r = rayBase + rl;
        cx = fmaf(3.0f, rays_d[r * 3 + 0], rays_o[r * 3 + 0]);
        cy = fmaf(3.0f, rays_d[r * 3 + 1], rays_o[r * 3 + 1]);
        cz = fmaf(3.0f, rays_d[r * 3 + 2], rays_o[r * 3 + 2]);
        C  = cx * cx + cy * cy + cz * cz;
    }
    if (t < RPB) sT[t] = 3.0e38f;
    __syncthreads();

    float best[KSEL];
    int   bidx[KSEL];
#pragma unroll
    for (int jj = 0; jj < KSEL; jj++) { best[jj] = 3.0e38f; bidx[jj] = 0; }
    float tloc = 3.0e38f;

    const int sliceLo = slice * SLICE;
    // Lane l stages point  4w + (l&3) + 16*(l>>2)  of each chunk into slot l.
    const int stagePt = 4 * w + (lane & 3) + 16 * (lane >> 2);
    const float4* src = g_packed + sliceLo + stagePt;

    // smem addresses (32-bit shared window)
    const uint32_t stWBase = (uint32_t)__cvta_generic_to_shared(stage) + (uint32_t)(w * NSTG * 32) * 16u;
    const uint32_t stWr    = stWBase + (uint32_t)lane * 16u;       // + buf*512
    const uint32_t stRd    = stWBase + (uint32_t)j * 16u;          // + buf*512 + u*64

    // Prologue: fill 4 stages
#pragma unroll
    for (int b = 0; b < NSTG; b++) {
        cpasync16(stWr + (uint32_t)b * 512u, src + b * CHPTS);
        cpcommit();
    }

    int pbase = sliceLo;                          // chunk start point index
#pragma unroll 1
    for (int c = 0; c < NCHUNK; c++) {
        const uint32_t rb = stRd + (uint32_t)(c & (NSTG - 1)) * 512u;
        cpwait3();                                // chunk c staged (c+1..c+3 in flight)
        __syncwarp();

        float Tl = fminf(sTv[rl], tloc);
        float s0, s1, s2, s3, s4, s5, s6, s7;
        {
            float4 q;
#define DOT(SS, U) \
            asm volatile("ld.shared.v4.f32 {%0,%1,%2,%3}, [%4];" \
                         : "=f"(q.x), "=f"(q.y), "=f"(q.z), "=f"(q.w) : "r"(rb + (U) * 64u)); \
            SS = fmaf(cx, q.x, fmaf(cy, q.y, fmaf(cz, q.z, q.w)));
            DOT(s0, 0) DOT(s1, 1) DOT(s2, 2) DOT(s3, 3)
            DOT(s4, 4) DOT(s5, 5) DOT(s6, 6) DOT(s7, 7)
#undef DOT
        }
        float m = fminf(fminf(fminf(s0, s1), fminf(s2, s3)),
                        fminf(fminf(s4, s5), fminf(s6, s7)));
        if (m < Tl) {
            float sv[UNR] = { s0, s1, s2, s3, s4, s5, s6, s7 };
#pragma unroll
            for (int u = 0; u < UNR; u++) {
                if (sv[u] < Tl) {
                    float v  = sv[u];
                    int   ii = pbase + sub + u * NSUB;
#pragma unroll
                    for (int jj = 0; jj < KSEL; jj++) {
                        if (v < best[jj]) {
                            float tv = best[jj]; int ti = bidx[jj];
                            best[jj] = v; bidx[jj] = ii;
                            v = tv; ii = ti;
                        }
                    }
                    tloc = best[KSEL - 1];
                    Tl   = fminf(Tl, tloc);
                }
            }
            if (tloc < sTv[rl]) sTv[rl] = tloc;   // benign race: any stored value is a valid bound
        }

        // Refill the stage we just consumed with chunk c+NSTG
        if (c + NSTG < NCHUNK)
            cpasync16(stWr + (uint32_t)(c & (NSTG - 1)) * 512u, src + (c + NSTG) * CHPTS);
        cpcommit();                               // always commit: keeps group counting aligned
        pbase += CHPTS;
    }
    cpwait0();
    __syncwarp();

    // Tail: 5 points per sub (direct LDG)
#pragma unroll 1
    for (int k = sliceLo + NCHUNK * CHPTS + sub; k < sliceLo + SLICE; k += NSUB) {
        float4 q = g_packed[k];
        float  s = fmaf(cx, q.x, fmaf(cy, q.y, fmaf(cz, q.z, q.w)));
        if (s < fminf(sTv[rl], tloc)) {
            float v = s; int ii = k;
#pragma unroll
            for (int jj = 0; jj < KSEL; jj++) {
                if (v < best[jj]) {
                    float tv = best[jj]; int ti = bidx[jj];
                    best[jj] = v; bidx[jj] = ii;
                    v = tv; ii = ti;
                }
            }
            tloc = best[KSEL - 1];
        }
    }

    const int lbase = (rl * NSUB + sub) * KSEL;
#pragma unroll
    for (int jj = 0; jj < KSEL; jj++) {
        md2s[lbase + jj]  = best[jj] + C;
        midxs[lbase + jj] = bidx[jj];
    }

    // Tree merge: 16 sorted lists -> 1 per ray
    for (int stride = NSUB / 2; stride >= 1; stride >>= 1) {
        __syncthreads();
        if (sub < stride) {
            int a = (rl * NSUB + sub) * KSEL;
            int b = (rl * NSUB + sub + stride) * KSEL;
            float ov[KSEL]; int oi[KSEL];
            int ia = 0, ib = 0;
#pragma unroll
            for (int k = 0; k < KSEL; k++) {
                float va = md2s[a + ia], vb = md2s[b + ib];
                if (va <= vb) { ov[k] = va; oi[k] = midxs[a + ia]; ia++; }
                else          { ov[k] = vb; oi[k] = midxs[b + ib]; ib++; }
            }
#pragma unroll
            for (int k = 0; k < KSEL; k++) { md2s[a + k] = ov[k]; midxs[a + k] = oi[k]; }
        }
    }
    __syncthreads();

    if (t < RPB) {
        int srcI = (t * NSUB) * KSEL;
        int dst  = (slice * BATCH + rayBase + t) * KSEL;
#pragma unroll
        for (int k = 0; k < KSEL; k++) {
            g_pd2 [dst + k] = md2s[srcI + k];
            g_pidx[dst + k] = midxs[srcI + k];
        }
    }
}

__global__ __launch_bounds__(128)
void finalize_kernel(const float* __restrict__ fdc,
                     const float* __restrict__ opac,
                     float* __restrict__ out)
{
    int ray = blockIdx.x * 128 + threadIdx.x;
    if (ray >= BATCH) return;
    int a = ray * KSEL, b = (BATCH + ray) * KSEL;
    int ia = 0, ib = 0;
    float wsum = 0.f, r0 = 0.f, g0 = 0.f, b0 = 0.f;
#pragma unroll
    for (int k = 0; k < KSEL; k++) {
        float va = (ia < KSEL) ? g_pd2[a + ia] : 3.0e38f;
        float vb = (ib < KSEL) ? g_pd2[b + ib] : 3.0e38f;
        float d2; int ii;
        if (va <= vb) { d2 = va; ii = g_pidx[a + ia]; ia++; }
        else          { d2 = vb; ii = g_pidx[b + ib]; ib++; }
        float d  = sqrtf(fmaxf(d2, 0.0f));
        float op = 1.0f / (1.0f + expf(-opac[ii]));
        float ww = expf(-0.1f * d) * op;
        wsum += ww;
        float c0 = 1.0f / (1.0f + expf(-fdc[ii * 3 + 0]));
        float c1 = 1.0f / (1.0f + expf(-fdc[ii * 3 + 1]));
        float c2 = 1.0f / (1.0f + expf(-fdc[ii * 3 + 2]));
        r0 = fmaf(ww, c0, r0);
        g0 = fmaf(ww, c1, g0);
        b0 = fmaf(ww, c2, b0);
    }
    float inv = 1.0f / (wsum + 1e-8f);
    out[ray * 3 + 0] = r0 * inv;
    out[ray * 3 + 1] = g0 * inv;
    out[ray * 3 + 2] = b0 * inv;
}

extern "C" void kernel_launch(void* const* d_in, const int* in_sizes, int n_in,
                              void* d_out, int out_size)
{
    const float* rays_o = (const float*)d_in[0];
    const float* rays_d = (const float*)d_in[1];
    const float* xyz    = (const float*)d_in[2];
    const float* fdc    = (const float*)d_in[3];
    const float* opac   = (const float*)d_in[4];
    float* out = (float*)d_out;

    pack_kernel<<<(NPTS + 255) / 256, 256>>>(xyz);
    scan_kernel<<<GRID, TPB>>>(rays_o, rays_d);
    finalize_kernel<<<BATCH / 128, 128>>>(fdc, opac, out);
}

// round 13
// speedup vs baseline: 1.5249x; 1.4378x over previous
#include <cuda_runtime.h>

#define NPTS     100000
#define BATCH    4096
#define KSEL     10
#define TPB      256
#define RPB      8
#define GRID     (BATCH / RPB)     // 512 blocks
#define SAMPLE   8192              // threshold sample size
#define CAP      704               // candidate capacity per ray (mean ~122, 14 sigma)
#define MITERS   195               // 195*256 = 49920 per half
#define HALF     49920
#define TAILBASE 99840             // tail: 160 points

__global__ __launch_bounds__(TPB)
void gs_kernel(const float* __restrict__ rays_o,
               const float* __restrict__ rays_d,
               const float* __restrict__ xyz,
               const float* __restrict__ fdc,
               const float* __restrict__ opac,
               float* __restrict__ out)
{
    __shared__ float scx[RPB], scy[RPB], scz[RPB], sC[RPB];
    __shared__ float sT[RPB];              // threshold (s-domain)
    __shared__ int   cnt[RPB];
    __shared__ float cd2 [RPB * CAP];      // phase1 merge lists / candidates / phase3 lists
    __shared__ int   cidx[RPB * CAP];
    volatile float* sTv = sT;

    const int t    = threadIdx.x;
    const int lane = t & 31;
    const int w    = t >> 5;               // warp 0..7
    const int rayBase = blockIdx.x * RPB;

    if (t < RPB) {
        int r = rayBase + t;
        float cx = fmaf(3.0f, rays_d[r*3+0], rays_o[r*3+0]);
        float cy = fmaf(3.0f, rays_d[r*3+1], rays_o[r*3+1]);
        float cz = fmaf(3.0f, rays_d[r*3+2], rays_o[r*3+2]);
        scx[t] = -2.0f * cx;               // packed: s = q + cx'*x + cy'*y + cz'*z
        scy[t] = -2.0f * cy;
        scz[t] = -2.0f * cz;
        sC[t]  = cx*cx + cy*cy + cz*cz;    // d^2 = s + C
        sT[t]  = 3.0e38f;
        cnt[t] = 0;
    }
    __syncthreads();

    // ---------- Phase 1: exact top-10 over SAMPLE points -> threshold ----------
    {
        const int rl  = t & 7;             // ray
        const int sub = t >> 3;            // 0..31
        const float cxp = scx[rl], cyp = scy[rl], czp = scz[rl];
        float best[KSEL];
#pragma unroll
        for (int j = 0; j < KSEL; j++) best[j] = 3.0e38f;
        float tloc = 3.0e38f;

#pragma unroll 4
        for (int c = 0; c < SAMPLE / 32; c++) {
            int k = sub + c * 32;
            float x = xyz[3*k+0], y = xyz[3*k+1], z = xyz[3*k+2];
            float q = fmaf(x, x, fmaf(y, y, z * z));
            float s = fmaf(cxp, x, fmaf(cyp, y, fmaf(czp, z, q)));
            if (s < fminf(sTv[rl], tloc)) {
                float v = s;
#pragma unroll
                for (int j = 0; j < KSEL; j++) {
                    if (v < best[j]) { float tv = best[j]; best[j] = v; v = tv; }
                }
                tloc = best[KSEL-1];
                if (tloc < sTv[rl]) sTv[rl] = tloc;   // benign race: any value is a valid bound
            }
        }
        float* smrg = cd2;                 // values-only merge lists
#pragma unroll
        for (int j = 0; j < KSEL; j++) smrg[(rl*32 + sub)*KSEL + j] = best[j];
        __syncthreads();

        for (int stride = 16; stride >= 1; stride >>= 1) {
            if (sub < stride) {
                int a = (rl*32 + sub)*KSEL, b = (rl*32 + sub + stride)*KSEL;
                float ov[KSEL]; int ia = 0, ib = 0;
#pragma unroll
                for (int k = 0; k < KSEL; k++) {
                    float va = smrg[a + ia], vb = smrg[b + ib];
                    if (va <= vb) { ov[k] = va; ia++; } else { ov[k] = vb; ib++; }
                }
#pragma unroll
                for (int k = 0; k < KSEL; k++) smrg[a + k] = ov[k];
            }
            __syncthreads();
        }
        if (t < RPB) { sT[t] = cd2[(t*32)*KSEL + KSEL-1]; cnt[t] = 0; }
        __syncthreads();
    }

    // ---------- Phase 2: lane-owned filter scan over all points ----------
    {
        const float c0x = scx[0], c0y = scy[0], c0z = scz[0], T0 = sT[0], C0 = sC[0];
        const float c1x = scx[1], c1y = scy[1], c1z = scz[1], T1 = sT[1], C1 = sC[1];
        const float c2x = scx[2], c2y = scy[2], c2z = scz[2], T2 = sT[2], C2 = sC[2];
        const float c3x = scx[3], c3y = scy[3], c3z = scz[3], T3 = sT[3], C3 = sC[3];
        const float c4x = scx[4], c4y = scy[4], c4z = scz[4], T4 = sT[4], C4 = sC[4];
        const float c5x = scx[5], c5y = scy[5], c5z = scz[5], T5 = sT[5], C5 = sC[5];
        const float c6x = scx[6], c6y = scy[6], c6z = scz[6], T6 = sT[6], C6 = sC[6];
        const float c7x = scx[7], c7y = scy[7], c7z = scz[7], T7 = sT[7], C7 = sC[7];

#define PUSH(SV, TR, CR, KK, R) \
        if ((SV) <= (TR)) { int _p = atomicAdd(&cnt[R], 1); \
            if (_p < CAP) { cd2[(R)*CAP + _p] = (SV) + (CR); cidx[(R)*CAP + _p] = (KK); } }

        const int stripe = w * 32 + lane;
#pragma unroll 1
        for (int it = 0; it < MITERS; it++) {
            int kA = stripe + it * 256;
            int kB = kA + HALF;
            float xA = xyz[3*kA+0], yA = xyz[3*kA+1], zA = xyz[3*kA+2];
            float xB = xyz[3*kB+0], yB = xyz[3*kB+1], zB = xyz[3*kB+2];
            float qA = fmaf(xA, xA, fmaf(yA, yA, zA * zA));
            float qB = fmaf(xB, xB, fmaf(yB, yB, zB * zB));

            float sA0 = fmaf(c0x,xA,fmaf(c0y,yA,fmaf(c0z,zA,qA)));
            float sA1 = fmaf(c1x,xA,fmaf(c1y,yA,fmaf(c1z,zA,qA)));
            float sA2 = fmaf(c2x,xA,fmaf(c2y,yA,fmaf(c2z,zA,qA)));
            float sA3 = fmaf(c3x,xA,fmaf(c3y,yA,fmaf(c3z,zA,qA)));
            float sA4 = fmaf(c4x,xA,fmaf(c4y,yA,fmaf(c4z,zA,qA)));
            float sA5 = fmaf(c5x,xA,fmaf(c5y,yA,fmaf(c5z,zA,qA)));
            float sA6 = fmaf(c6x,xA,fmaf(c6y,yA,fmaf(c6z,zA,qA)));
            float sA7 = fmaf(c7x,xA,fmaf(c7y,yA,fmaf(c7z,zA,qA)));
            float sB0 = fmaf(c0x,xB,fmaf(c0y,yB,fmaf(c0z,zB,qB)));
            float sB1 = fmaf(c1x,xB,fmaf(c1y,yB,fmaf(c1z,zB,qB)));
            float sB2 = fmaf(c2x,xB,fmaf(c2y,yB,fmaf(c2z,zB,qB)));
            float sB3 = fmaf(c3x,xB,fmaf(c3y,yB,fmaf(c3z,zB,qB)));
            float sB4 = fmaf(c4x,xB,fmaf(c4y,yB,fmaf(c4z,zB,qB)));
            float sB5 = fmaf(c5x,xB,fmaf(c5y,yB,fmaf(c5z,zB,qB)));
            float sB6 = fmaf(c6x,xB,fmaf(c6y,yB,fmaf(c6z,zB,qB)));
            float sB7 = fmaf(c7x,xB,fmaf(c7y,yB,fmaf(c7z,zB,qB)));

            int hA = (sA0<=T0) | (sA1<=T1) | (sA2<=T2) | (sA3<=T3)
                   | (sA4<=T4) | (sA5<=T5) | (sA6<=T6) | (sA7<=T7);
            int hB = (sB0<=T0) | (sB1<=T1) | (sB2<=T2) | (sB3<=T3)
                   | (sB4<=T4) | (sB5<=T5) | (sB6<=T6) | (sB7<=T7);
            if (hA | hB) {
                if (hA) {
                    PUSH(sA0,T0,C0,kA,0) PUSH(sA1,T1,C1,kA,1)
                    PUSH(sA2,T2,C2,kA,2) PUSH(sA3,T3,C3,kA,3)
                    PUSH(sA4,T4,C4,kA,4) PUSH(sA5,T5,C5,kA,5)
                    PUSH(sA6,T6,C6,kA,6) PUSH(sA7,T7,C7,kA,7)
                }
                if (hB) {
                    PUSH(sB0,T0,C0,kB,0) PUSH(sB1,T1,C1,kB,1)
                    PUSH(sB2,T2,C2,kB,2) PUSH(sB3,T3,C3,kB,3)
                    PUSH(sB4,T4,C4,kB,4) PUSH(sB5,T5,C5,kB,5)
                    PUSH(sB6,T6,C6,kB,6) PUSH(sB7,T7,C7,kB,7)
                }
            }
        }
        // Tail: 160 points, one per thread
        if (t < NPTS - TAILBASE) {
            int k = TAILBASE + t;
            float x = xyz[3*k+0], y = xyz[3*k+1], z = xyz[3*k+2];
            float q = fmaf(x, x, fmaf(y, y, z * z));
            float s0 = fmaf(c0x,x,fmaf(c0y,y,fmaf(c0z,z,q)));
            float s1 = fmaf(c1x,x,fmaf(c1y,y,fmaf(c1z,z,q)));
            float s2 = fmaf(c2x,x,fmaf(c2y,y,fmaf(c2z,z,q)));
            float s3 = fmaf(c3x,x,fmaf(c3y,y,fmaf(c3z,z,q)));
            float s4 = fmaf(c4x,x,fmaf(c4y,y,fmaf(c4z,z,q)));
            float s5 = fmaf(c5x,x,fmaf(c5y,y,fmaf(c5z,z,q)));
            float s6 = fmaf(c6x,x,fmaf(c6y,y,fmaf(c6z,z,q)));
            float s7 = fmaf(c7x,x,fmaf(c7y,y,fmaf(c7z,z,q)));
            PUSH(s0,T0,C0,k,0) PUSH(s1,T1,C1,k,1) PUSH(s2,T2,C2,k,2) PUSH(s3,T3,C3,k,3)
            PUSH(s4,T4,C4,k,4) PUSH(s5,T5,C5,k,5) PUSH(s6,T6,C6,k,6) PUSH(s7,T7,C7,k,7)
        }
#undef PUSH
    }
    __syncthreads();

    // ---------- Phase 3: warp w selects exact top-10 of ray w ----------
    {
        int n = cnt[w]; if (n > CAP) n = CAP;
        float best[KSEL]; int bxi[KSEL];
#pragma unroll
        for (int j = 0; j < KSEL; j++) { best[j] = 3.0e38f; bxi[j] = 0; }
        for (int j2 = lane; j2 < n; j2 += 32) {
            float v = cd2[w*CAP + j2]; int ii = cidx[w*CAP + j2];
            if (v < best[KSEL-1]) {
#pragma unroll
                for (int j = 0; j < KSEL; j++) {
                    if (v < best[j]) {
                        float tv = best[j]; int ti = bxi[j];
                        best[j] = v; bxi[j] = ii; v = tv; ii = ti;
                    }
                }
            }
        }
        __syncwarp();                       // all candidate reads done before overwrite
#pragma unroll
        for (int j = 0; j < KSEL; j++) {
            cd2 [w*CAP + lane*KSEL + j] = best[j];
            cidx[w*CAP + lane*KSEL + j] = bxi[j];
        }
        __syncwarp();
        for (int stride = 16; stride >= 1; stride >>= 1) {
            if (lane < stride) {
                int a = w*CAP + lane*KSEL, b = w*CAP + (lane + stride)*KSEL;
                float ov[KSEL]; int oi[KSEL];
                int ia = 0, ib = 0;
#pragma unroll
                for (int k = 0; k < KSEL; k++) {
                    float va = cd2[a + ia], vb = cd2[b + ib];
                    if (va <= vb) { ov[k] = va; oi[k] = cidx[a + ia]; ia++; }
                    else          { ov[k] = vb; oi[k] = cidx[b + ib]; ib++; }
                }
#pragma unroll
                for (int k = 0; k < KSEL; k++) { cd2[a + k] = ov[k]; cidx[a + k] = oi[k]; }
            }
            __syncwarp();
        }
        if (lane == 0) {
            float wsum = 0.f, r0 = 0.f, g0 = 0.f, b0 = 0.f;
#pragma unroll
            for (int k = 0; k < KSEL; k++) {
                float d2 = cd2[w*CAP + k];
                int   ii = cidx[w*CAP + k];
                float d  = sqrtf(fmaxf(d2, 0.0f));
                float op = 1.0f / (1.0f + expf(-opac[ii]));
                float ww = expf(-0.1f * d) * op;
                wsum += ww;
                float a0 = 1.0f / (1.0f + expf(-fdc[ii*3+0]));
                float a1 = 1.0f / (1.0f + expf(-fdc[ii*3+1]));
                float a2 = 1.0f / (1.0f + expf(-fdc[ii*3+2]));
                r0 = fmaf(ww, a0, r0);
                g0 = fmaf(ww, a1, g0);
                b0 = fmaf(ww, a2, b0);
            }
            float inv = 1.0f / (wsum + 1e-8f);
            int ray = rayBase + w;
            out[ray*3+0] = r0 * inv;
            out[ray*3+1] = g0 * inv;
            out[ray*3+2] = b0 * inv;
        }
    }
}

extern "C" void kernel_launch(void* const* d_in, const int* in_sizes, int n_in,
                              void* d_out, int out_size)
{
    const float* rays_o = (const float*)d_in[0];
    const float* rays_d = (const float*)d_in[1];
    const float* xyz    = (const float*)d_in[2];
    const float* fdc    = (const float*)d_in[3];
    const float* opac   = (const float*)d_in[4];
    float* out = (float*)d_out;

    gs_kernel<<<GRID, TPB>>>(rays_o, rays_d, xyz, fdc, opac, out);
}